// round 14
// baseline (speedup 1.0000x reference)
#include <cuda_runtime.h>

// Single fused persistent kernel, zero FP64 at runtime.
// out[n][d] = (x[n]==0 ? 0 : W[x[n]][d]) + PE(n,d)
// Seed path: compile-time two-float w table + fp32 EFT + Cody-Waite + MUFU,
// recomputed per chunk (measured cost: ~0 vs table version).
// Scheduling: 512 resident CTAs (4/SM), each handles exactly nchunks/512
// chunks -> no wave tail. Hot loop: G=8 batched __ldg gathers (plain; L2
// policy hints measured neutral twice), evict-first streaming stores,
// fp32 rotation recurrence, exact reseed every 128 rows.

#define D_DIM   1024
#define TPB     256
#define ROWS    128
#define G       8
#define GRID_P  512          // persistent grid: 512 <= 148 SMs * 4 CTAs

// ---- compile-time construction of w = r^k as two-float ----
constexpr double cexp_small(double x) {       // |x|<0.02: Taylor, full DP prec
    double t = 1.0, term = 1.0;
    for (int i = 1; i < 22; i++) { term *= x / (double)i; t += term; }
    return t;
}
constexpr double cpow_u(double base, int n) { // binary exponentiation
    double acc = 1.0, b = base;
    while (n) { if (n & 1) acc *= b; b *= b; n >>= 1; }
    return acc;
}
constexpr double R_STEP = cexp_small(-9.210340371976184 / 512.0); // 10000^{-1/512}

#define CW(k)  cpow_u(R_STEP, (k))
#define WHI(k) ((float)CW(k))
#define WLO(k) ((float)(CW(k) - (double)((float)CW(k))))
#define W2(k)  { WHI(k), WLO(k) }
#define W2R(b) W2(b+0),W2(b+1),W2(b+2),W2(b+3),W2(b+4),W2(b+5),W2(b+6),W2(b+7), \
               W2(b+8),W2(b+9),W2(b+10),W2(b+11),W2(b+12),W2(b+13),W2(b+14),W2(b+15), \
               W2(b+16),W2(b+17),W2(b+18),W2(b+19),W2(b+20),W2(b+21),W2(b+22),W2(b+23), \
               W2(b+24),W2(b+25),W2(b+26),W2(b+27),W2(b+28),W2(b+29),W2(b+30),W2(b+31)

__device__ const float2 g_w2[513] = {
    W2R(0),   W2R(32),  W2R(64),  W2R(96),  W2R(128), W2R(160), W2R(192), W2R(224),
    W2R(256), W2R(288), W2R(320), W2R(352), W2R(384), W2R(416), W2R(448), W2R(480),
    W2(512)
};

__global__ __launch_bounds__(TPB, 4)
void pe_embed_persist(const int* __restrict__ x,
                      const float* __restrict__ W,
                      float* __restrict__ out,
                      int N, int nchunks)
{
    __shared__ int sx[ROWS];

    const int t = threadIdx.x;
    const float4* __restrict__ Wv = (const float4*)W;
    float4* outv = (float4*)out;

    // w table entries for this thread (chunk-invariant)
    float2 wv0, wv1, wv2;
    {
        wv0 = __ldg(&g_w2[2 * t + 0]);
        wv1 = __ldg(&g_w2[2 * t + 1]);
        wv2 = __ldg(&g_w2[2 * t + 2]);
    }
    // per-row rotation constants (chunk-invariant)
    float sw[3], cw[3];
    __sincosf(wv0.x + wv0.y, &sw[0], &cw[0]);
    __sincosf(wv1.x + wv1.y, &sw[1], &cw[1]);
    __sincosf(wv2.x + wv2.y, &sw[2], &cw[2]);

    for (int chunk = blockIdx.x; chunk < nchunks; chunk += GRID_P) {
        const int n0 = chunk * ROWS;

        __syncthreads();                      // prior chunk's readers done
        if (t < ROWS) {
            int n = n0 + t;
            sx[t] = (n < N) ? x[n] : 0;
        }

        // seed the 3 rotation states for this chunk
        float s[3], c[3];
        {
            const float INV_2PI = 0.15915494309189535f;
            const float C1 = 6.28125f;               // 201/32: k*C1 exact, k<2^15
            const float C2 = 1.9353071795864770e-3f; // 2pi - C1
            const float p  = (float)(n0 + 1);        // exact: < 2^17
            float2 wvm[3] = { wv0, wv1, wv2 };
#pragma unroll
            for (int m = 0; m < 3; m++) {
                float hi  = p * wvm[m].x;
                float err = fmaf(p, wvm[m].x, -hi);  // exact residual
                float lo  = fmaf(p, wvm[m].y, err);
                float k = rintf(hi * INV_2PI);
                float r = fmaf(-k, C1, hi);
                r = fmaf(-k, C2, r);
                r += lo;
                __sincosf(r, &s[m], &c[m]);
            }
        }
        __syncthreads();

        const int nr = (N - n0 < ROWS) ? (N - n0) : ROWS;
        const long obase = (long)n0 * (D_DIM / 4) + t;

        if (nr == ROWS) {
            for (int rb = 0; rb < ROWS; rb += G) {
                int    idx[G];
                float4 e[G];
#pragma unroll
                for (int j = 0; j < G; j++) idx[j] = sx[rb + j];
#pragma unroll
                for (int j = 0; j < G; j++)  // unconditional: row 0 valid memory
                    e[j] = __ldg(&Wv[(long)idx[j] * (D_DIM / 4) + t]);
#pragma unroll
                for (int j = 0; j < G; j++) {
                    float msk = (idx[j] == 0) ? 0.f : 1.f;  // padding row -> 0
                    float4 o;
                    o.x = fmaf(e[j].x, msk, c[0]);
                    o.y = fmaf(e[j].y, msk, s[1]);
                    o.z = fmaf(e[j].z, msk, c[1]);
                    o.w = fmaf(e[j].w, msk, s[2]);
                    __stcs(&outv[obase + (long)(rb + j) * (D_DIM / 4)], o);
#pragma unroll
                    for (int m = 0; m < 3; m++) {
                        float ns = fmaf(s[m], cw[m],  c[m] * sw[m]);
                        float nc = fmaf(c[m], cw[m], -s[m] * sw[m]);
                        s[m] = ns; c[m] = nc;
                    }
                }
            }
        } else {
            for (int r = 0; r < nr; r++) {
                int idx = sx[r];
                float4 e = make_float4(0.f, 0.f, 0.f, 0.f);
                if (idx != 0) e = __ldg(&Wv[(long)idx * (D_DIM / 4) + t]);
                float4 o;
                o.x = e.x + c[0];
                o.y = e.y + s[1];
                o.z = e.z + c[1];
                o.w = e.w + s[2];
                __stcs(&outv[obase + (long)r * (D_DIM / 4)], o);
#pragma unroll
                for (int m = 0; m < 3; m++) {
                    float ns = fmaf(s[m], cw[m],  c[m] * sw[m]);
                    float nc = fmaf(c[m], cw[m], -s[m] * sw[m]);
                    s[m] = ns; c[m] = nc;
                }
            }
        }
    }
}

extern "C" void kernel_launch(void* const* d_in, const int* in_sizes, int n_in,
                              void* d_out, int out_size)
{
    const int*   x;
    const float* W;
    int N;
    if (in_sizes[0] < in_sizes[1]) {
        x = (const int*)d_in[0];  W = (const float*)d_in[1];  N = in_sizes[0];
    } else {
        x = (const int*)d_in[1];  W = (const float*)d_in[0];  N = in_sizes[1];
    }
    int nchunks = (N + ROWS - 1) / ROWS;
    int grid = (nchunks < GRID_P) ? nchunks : GRID_P;
    pe_embed_persist<<<grid, TPB>>>(x, W, (float*)d_out, N, nchunks);
}